// round 11
// baseline (speedup 1.0000x reference)
#include <cuda_runtime.h>
#include <cuda_bf16.h>
#include <cstdint>

#define NN 50000
#define NE 800000
#define NG 512
#define H  128
#define NL 4

#define SCAN_B  128
#define SCAN_NB ((NN + SCAN_B - 1) / SCAN_B)   // 391

// padded bf16 row length for B tiles (ldmatrix-friendly, conflict-free)
#define LDK 136
#define PLANE (128 * LDK)                      // elements per plane
#define BBYTES (PLANE * 2 * 2)                 // hi+lo planes, bytes (69632)

// ---------------- device scratch (static, no allocations) ----------------
__device__ float g_x  [(size_t)NN * H];
__device__ uint2 g_aggs[(size_t)NN * 64];      // split(agg): {hi bf16x2, lo bf16x2} per col pair
__device__ uint2 g_ys  [(size_t)NN * 64];      // split(y)
__device__ float g_pool[(size_t)NG * H];
__device__ float g_ho [4 * NG];
__device__ float g_T   [100 * H];     // embed_tab @ Wc0
__device__ float g_Weff[3 * H];       // W_pos @ Wc1
__device__ float g_beff[H];           // b_pos @ Wc1 + b_comb
// pre-split weights: 8 matrices x (hi plane + lo plane), [n][LDK] bf16
__device__ uint4 g_wt[(size_t)8 * BBYTES / 16];
// CSR scratch
__device__ int g_deg   [NN];
__device__ int g_rowptr[NN + 1];
__device__ int g_cursor[NN];
__device__ int g_col   [NE];
__device__ int g_part  [SCAN_NB];

// ---------------- helpers ----------------
__device__ __forceinline__ uint32_t smem_to_u32(const void* p) {
    uint32_t a;
    asm("{ .reg .u64 t; cvta.to.shared.u64 t, %1; cvt.u32.u64 %0, t; }" : "=r"(a) : "l"(p));
    return a;
}
__device__ __forceinline__ uint32_t pack_bf16x2(float lo_elem, float hi_elem) {
    uint32_t r;
    asm("cvt.rn.bf16x2.f32 %0, %1, %2;" : "=r"(r) : "f"(hi_elem), "f"(lo_elem));
    return r;
}
__device__ __forceinline__ void split2(float fx, float fy, uint32_t& hi, uint32_t& lo) {
    hi = pack_bf16x2(fx, fy);
    float hx = __uint_as_float(hi << 16);
    float hy = __uint_as_float(hi & 0xFFFF0000u);
    lo = pack_bf16x2(fx - hx, fy - hy);
}
__device__ __forceinline__ void ldsm_x4(uint32_t addr, uint32_t& r0, uint32_t& r1,
                                        uint32_t& r2, uint32_t& r3) {
    asm volatile("ldmatrix.sync.aligned.m8n8.x4.shared.b16 {%0,%1,%2,%3}, [%4];"
                 : "=r"(r0), "=r"(r1), "=r"(r2), "=r"(r3) : "r"(addr));
}
__device__ __forceinline__ void mma16816(float* c, const uint32_t* a, const uint32_t* b) {
    asm volatile("mma.sync.aligned.m16n8k16.row.col.f32.bf16.bf16.f32 "
                 "{%0,%1,%2,%3}, {%4,%5,%6,%7}, {%8,%9}, {%0,%1,%2,%3};"
                 : "+f"(c[0]), "+f"(c[1]), "+f"(c[2]), "+f"(c[3])
                 : "r"(a[0]), "r"(a[1]), "r"(a[2]), "r"(a[3]), "r"(b[0]), "r"(b[1]));
}
__device__ __forceinline__ float softplusf(float x) {
    return fmaxf(x, 0.f) + log1pf(expf(-fabsf(x)));
}
__device__ __forceinline__ int lbound(const int* __restrict__ a, int n, int v) {
    int lo = 0, hi = n;
    while (lo < hi) { int m = (lo + hi) >> 1; if (a[m] < v) lo = m + 1; else hi = m; }
    return lo;
}

// ---------------- init-stage folding ----------------
__global__ void prep_init_kernel(const float* __restrict__ tab, const float* __restrict__ Wp,
                                 const float* __restrict__ bp, const float* __restrict__ Wcomb,
                                 const float* __restrict__ bcomb,
                                 float* __restrict__ T, float* __restrict__ Weff,
                                 float* __restrict__ beff) {
    int gid = blockIdx.x * blockDim.x + threadIdx.x;
    if (gid >= 104 * H) return;
    int r = gid >> 7;
    int c = gid & 127;
    if (r < 100) {
        float s = 0.f;
        for (int k = 0; k < H; k++) s = fmaf(tab[(size_t)r * H + k], Wcomb[(size_t)k * H + c], s);
        T[(size_t)r * H + c] = s;
    } else if (r < 103) {
        int d = r - 100;
        float s = 0.f;
        for (int k = 0; k < H; k++) s = fmaf(Wp[(size_t)d * H + k], Wcomb[(size_t)(H + k) * H + c], s);
        Weff[(size_t)d * H + c] = s;
    } else {
        float s = bcomb[c];
        for (int k = 0; k < H; k++) s = fmaf(bp[k], Wcomb[(size_t)(H + k) * H + c], s);
        beff[c] = s;
    }
}

__global__ void x_init_kernel(const int* __restrict__ z, const float* __restrict__ pos,
                              const float* __restrict__ T, const float* __restrict__ Weff,
                              const float* __restrict__ beff, float* __restrict__ x) {
    int gid = blockIdx.x * blockDim.x + threadIdx.x;
    if (gid >= NN * 32) return;
    int i = gid >> 5;
    int c = (gid & 31) * 4;
    float p0 = pos[i * 3 + 0], p1 = pos[i * 3 + 1], p2 = pos[i * 3 + 2];
    float4 tv = *(const float4*)(T + (size_t)z[i] * H + c);
    float4 w0 = *(const float4*)(Weff + 0 * H + c);
    float4 w1 = *(const float4*)(Weff + 1 * H + c);
    float4 w2 = *(const float4*)(Weff + 2 * H + c);
    float4 bb = *(const float4*)(beff + c);
    float4 v;
    v.x = fmaxf(tv.x + p0 * w0.x + p1 * w1.x + p2 * w2.x + bb.x, 0.f);
    v.y = fmaxf(tv.y + p0 * w0.y + p1 * w1.y + p2 * w2.y + bb.y, 0.f);
    v.z = fmaxf(tv.z + p0 * w0.z + p1 * w1.z + p2 * w2.z + bb.z, 0.f);
    v.w = fmaxf(tv.w + p0 * w0.w + p1 * w1.w + p2 * w2.w + bb.w, 0.f);
    *(float4*)(x + (size_t)i * H + c) = v;
}

// ---------------- CSR build ----------------
__global__ void zero_int_kernel(int* __restrict__ p, int n) {
    int i = blockIdx.x * blockDim.x + threadIdx.x;
    if (i < n) p[i] = 0;
}
__global__ void deg_kernel(const int* __restrict__ dst, int* __restrict__ deg) {
    int e = blockIdx.x * blockDim.x + threadIdx.x;
    if (e < NE) atomicAdd(deg + dst[e], 1);
}
__global__ void partial_kernel(const int* __restrict__ deg, int* __restrict__ part) {
    __shared__ int sh[SCAN_B];
    int b = blockIdx.x, t = threadIdx.x, i = b * SCAN_B + t;
    sh[t] = (i < NN) ? deg[i] : 0;
    __syncthreads();
    for (int off = SCAN_B / 2; off > 0; off >>= 1) {
        if (t < off) sh[t] += sh[t + off];
        __syncthreads();
    }
    if (t == 0) part[b] = sh[0];
}
__global__ void scanpart_kernel(int* __restrict__ part, int* __restrict__ rowptr) {
    __shared__ int sh[512];
    int t = threadIdx.x;
    sh[t] = (t < SCAN_NB) ? part[t] : 0;
    __syncthreads();
    for (int off = 1; off < 512; off <<= 1) {
        int v = (t >= off) ? sh[t - off] : 0;
        __syncthreads();
        sh[t] += v;
        __syncthreads();
    }
    if (t < SCAN_NB) part[t] = (t == 0) ? 0 : sh[t - 1];
    if (t == 0) rowptr[NN] = NE;
}
__global__ void rowptr_kernel(const int* __restrict__ deg, const int* __restrict__ part,
                              int* __restrict__ rowptr, int* __restrict__ cursor) {
    __shared__ int sh[SCAN_B];
    int b = blockIdx.x, t = threadIdx.x, i = b * SCAN_B + t;
    sh[t] = (i < NN) ? deg[i] : 0;
    __syncthreads();
    for (int off = 1; off < SCAN_B; off <<= 1) {
        int v = (t >= off) ? sh[t - off] : 0;
        __syncthreads();
        sh[t] += v;
        __syncthreads();
    }
    if (i < NN) {
        int excl = part[b] + ((t == 0) ? 0 : sh[t - 1]);
        rowptr[i] = excl;
        cursor[i] = excl;
    }
}
__global__ void fill_kernel(const int* __restrict__ src, const int* __restrict__ dst,
                            int* __restrict__ cursor, int* __restrict__ col) {
    int e = blockIdx.x * blockDim.x + threadIdx.x;
    if (e < NE) {
        int p = atomicAdd(cursor + dst[e], 1);
        col[p] = src[e];
    }
}

// ---------------- gather: agg_split[i] = split(x[i] + sum_{j in N(i)} x[j]) ----------------
__global__ __launch_bounds__(256)
void gather_kernel(const float* __restrict__ x, const int* __restrict__ rowptr,
                   const int* __restrict__ col, uint2* __restrict__ aggs) {
    int node = blockIdx.x * 8 + (threadIdx.x >> 5);
    if (node >= NN) return;
    int lane = threadIdx.x & 31;
    int beg = rowptr[node];
    int end = rowptr[node + 1];
    const float* xr = x + (size_t)lane * 4;
    float4 acc = *(const float4*)(x + (size_t)node * H + lane * 4);
    float4 acc2 = make_float4(0.f, 0.f, 0.f, 0.f);
    int j = beg;
    for (; j + 3 < end; j += 4) {
        int s0 = col[j], s1 = col[j + 1], s2 = col[j + 2], s3 = col[j + 3];
        float4 a = *(const float4*)(xr + (size_t)s0 * H);
        float4 b = *(const float4*)(xr + (size_t)s1 * H);
        float4 c = *(const float4*)(xr + (size_t)s2 * H);
        float4 d = *(const float4*)(xr + (size_t)s3 * H);
        acc.x += a.x + b.x;  acc.y += a.y + b.y;
        acc.z += a.z + b.z;  acc.w += a.w + b.w;
        acc2.x += c.x + d.x; acc2.y += c.y + d.y;
        acc2.z += c.z + d.z; acc2.w += c.w + d.w;
    }
    for (; j < end; j++) {
        int s0 = col[j];
        float4 a = *(const float4*)(xr + (size_t)s0 * H);
        acc.x += a.x; acc.y += a.y; acc.z += a.z; acc.w += a.w;
    }
    acc.x += acc2.x; acc.y += acc2.y; acc.z += acc2.z; acc.w += acc2.w;
    uint2 o0, o1;
    split2(acc.x, acc.y, o0.x, o0.y);
    split2(acc.z, acc.w, o1.x, o1.y);
    aggs[(size_t)node * 64 + lane * 2 + 0] = o0;
    aggs[(size_t)node * 64 + lane * 2 + 1] = o1;
}

// ---------------- weight prep: transpose + bf16 hi/lo split, padded [n][LDK] ----------------
__global__ void prep_weights_kernel(const float* __restrict__ gW1, const float* __restrict__ gW2,
                                    __nv_bfloat16* __restrict__ wt) {
    int gid = blockIdx.x * blockDim.x + threadIdx.x;
    if (gid >= 8 * 16384) return;
    int mat = gid >> 14;
    int k   = (gid >> 7) & 127;
    int n   = gid & 127;
    const float* Wsrc = (mat < 4) ? gW1 + (size_t)mat * 16384
                                  : gW2 + (size_t)(mat - 4) * 16384;
    float v = Wsrc[(size_t)k * 128 + n];       // B[n][k] = W[k][n]
    float h = __bfloat162float(__float2bfloat16(v));
    float l = v - h;
    __nv_bfloat16* base = wt + (size_t)mat * 2 * PLANE;
    base[(size_t)n * LDK + k]         = __float2bfloat16(h);
    base[PLANE + (size_t)n * LDK + k] = __float2bfloat16(l);
}

// ---------------- HMMA GEMM: C = act(A @ W + bias) ----------------
// A operand in pre-split form (uint2 {hi,lo} per col pair) - zero conversion
// instructions in the mainloop. B (hi+lo planes) in smem. 2 CTAs/SM.
#define SM_B_HI 0
#define SM_B_LO (PLANE * 2)
#define GEMM_SMEM BBYTES        // 69632 bytes

template<bool RELU, bool SPLITOUT>
__global__ __launch_bounds__(256, 2)
void gemm_tc_kernel(const uint2* __restrict__ As, const uint4* __restrict__ Bt,
                    const float* __restrict__ bias, float* __restrict__ C,
                    uint2* __restrict__ Cs, int M) {
    extern __shared__ char smem[];
    uint32_t sb = smem_to_u32(smem);
    int t = threadIdx.x, wid = t >> 5, lane = t & 31;
    int m0 = blockIdx.x * 128;

    for (int i = t; i < BBYTES / 16; i += 256) {
        uint32_t d = sb + i * 16;
        asm volatile("cp.async.cg.shared.global [%0], [%1], 16;"
                     :: "r"(d), "l"(Bt + i) : "memory");
    }
    asm volatile("cp.async.commit_group;" ::: "memory");

    int mrow0 = (wid >> 1) * 32;
    int ncol0 = (wid & 1) * 64;
    int g  = lane >> 2;
    int tp = lane & 3;               // col-pair offset within k-group

    int r0 = min(m0 + mrow0 + g,      M - 1);
    int r1 = min(m0 + mrow0 + g + 8,  M - 1);
    int r2 = min(m0 + mrow0 + g + 16, M - 1);
    int r3 = min(m0 + mrow0 + g + 24, M - 1);
    const uint2* q00 = As + (size_t)r0 * 64 + tp;
    const uint2* q01 = As + (size_t)r1 * 64 + tp;
    const uint2* q10 = As + (size_t)r2 * 64 + tp;
    const uint2* q11 = As + (size_t)r3 * 64 + tp;

    // prefetch kk=0 while B cp.async is in flight
    uint2 cur[8];
    cur[0] = q00[0]; cur[1] = q00[4];
    cur[2] = q01[0]; cur[3] = q01[4];
    cur[4] = q10[0]; cur[5] = q10[4];
    cur[6] = q11[0]; cur[7] = q11[4];

    asm volatile("cp.async.wait_group 0;" ::: "memory");
    __syncthreads();

    // ldmatrix.x4 lane addressing: j = lane>>3 selects matrix
    int jm = lane >> 3;
    uint32_t bb = ((uint32_t)(ncol0 + (jm >> 1) * 8 + (lane & 7)) * LDK + (jm & 1) * 8) * 2;
    uint32_t aBh = sb + SM_B_HI + bb;
    uint32_t aBl = sb + SM_B_LO + bb;

    float acc[2][8][4];
#pragma unroll
    for (int mi = 0; mi < 2; mi++)
#pragma unroll
        for (int nf = 0; nf < 8; nf++)
#pragma unroll
            for (int q = 0; q < 4; q++) acc[mi][nf][q] = 0.f;

#pragma unroll
    for (int kk = 0; kk < 8; kk++) {
        uint32_t ko = kk * 32;           // bytes
        uint2 nxt[8];
        if (kk < 7) {
            int kp = (kk + 1) * 8;
            nxt[0] = q00[kp];     nxt[1] = q00[kp + 4];
            nxt[2] = q01[kp];     nxt[3] = q01[kp + 4];
            nxt[4] = q10[kp];     nxt[5] = q10[kp + 4];
            nxt[6] = q11[kp];     nxt[7] = q11[kp + 4];
        }
        uint32_t ah[2][4], al[2][4];
        ah[0][0] = cur[0].x; al[0][0] = cur[0].y;
        ah[0][1] = cur[2].x; al[0][1] = cur[2].y;
        ah[0][2] = cur[1].x; al[0][2] = cur[1].y;
        ah[0][3] = cur[3].x; al[0][3] = cur[3].y;
        ah[1][0] = cur[4].x; al[1][0] = cur[4].y;
        ah[1][1] = cur[6].x; al[1][1] = cur[6].y;
        ah[1][2] = cur[5].x; al[1][2] = cur[5].y;
        ah[1][3] = cur[7].x; al[1][3] = cur[7].y;
#pragma unroll
        for (int nfp = 0; nfp < 4; nfp++) {
            uint32_t bh[4], bl[4];
            ldsm_x4(aBh + nfp * (16 * LDK * 2) + ko, bh[0], bh[1], bh[2], bh[3]);
            ldsm_x4(aBl + nfp * (16 * LDK * 2) + ko, bl[0], bl[1], bl[2], bl[3]);
#pragma unroll
            for (int mi = 0; mi < 2; mi++) {
                mma16816(acc[mi][2 * nfp + 0], ah[mi], bh);
                mma16816(acc[mi][2 * nfp + 0], ah[mi], bl);
                mma16816(acc[mi][2 * nfp + 0], al[mi], bh);
                mma16816(acc[mi][2 * nfp + 1], ah[mi], bh + 2);
                mma16816(acc[mi][2 * nfp + 1], ah[mi], bl + 2);
                mma16816(acc[mi][2 * nfp + 1], al[mi], bh + 2);
            }
        }
#pragma unroll
        for (int j = 0; j < 8; j++) cur[j] = nxt[j];
    }

    // epilogue
    int rbase = mrow0 + (lane >> 2);
    int cbase = ncol0 + (lane & 3) * 2;
#pragma unroll
    for (int mi = 0; mi < 2; mi++) {
#pragma unroll
        for (int half = 0; half < 2; half++) {
            int row = rbase + mi * 16 + half * 8;
            int m = m0 + row;
            if (m >= M) continue;
#pragma unroll
            for (int nf = 0; nf < 8; nf++) {
                int colc = cbase + nf * 8;
                float2 v;
                v.x = acc[mi][nf][half * 2 + 0];
                v.y = acc[mi][nf][half * 2 + 1];
                float2 b2 = *(const float2*)(bias + colc);
                v.x += b2.x; v.y += b2.y;
                if (RELU) { v.x = fmaxf(v.x, 0.f); v.y = fmaxf(v.y, 0.f); }
                if (SPLITOUT) {
                    uint2 o;
                    split2(v.x, v.y, o.x, o.y);
                    Cs[(size_t)m * 64 + (colc >> 1)] = o;
                } else {
                    *(float2*)(C + (size_t)m * 128 + colc) = v;
                }
            }
        }
    }
}

// ---------------- pooling / heads / epilogue ----------------
__global__ void pool_kernel(const float* __restrict__ x, const int* __restrict__ batch,
                            float* __restrict__ pool) {
    int g = blockIdx.x, f = threadIdx.x;
    __shared__ int slo, shi;
    if (f == 0) { slo = lbound(batch, NN, g); shi = lbound(batch, NN, g + 1); }
    __syncthreads();
    float s = 0.f;
    for (int i = slo; i < shi; i++) s += x[(size_t)i * H + f];
    pool[(size_t)g * H + f] = s;
}

__global__ void heads_kernel(const float* __restrict__ pool, const float* __restrict__ W1,
                             const float* __restrict__ b1, const float* __restrict__ W2,
                             const float* __restrict__ b2, float* __restrict__ hout) {
    int k = blockIdx.x, gc = blockIdx.y, f = threadIdx.x;
    __shared__ float rows[16][128];
    __shared__ float red[16][128];
    int g0 = gc * 16;
#pragma unroll
    for (int g = 0; g < 16; g++) rows[g][f] = pool[(size_t)(g0 + g) * H + f];
    __syncthreads();
    const float* W1k = W1 + (size_t)k * H * H;
    float acc[16];
#pragma unroll
    for (int g = 0; g < 16; g++) acc[g] = 0.f;
    for (int h = 0; h < 128; h++) {
        float w = W1k[(size_t)h * H + f];
#pragma unroll
        for (int g = 0; g < 16; g++) acc[g] = fmaf(rows[g][h], w, acc[g]);
    }
    float bb = b1[k * H + f];
    float w2 = W2[k * H + f];
#pragma unroll
    for (int g = 0; g < 16; g++) red[g][f] = fmaxf(acc[g] + bb, 0.f) * w2;
    __syncthreads();
    if (f < 16) {
        float s = 0.f;
        for (int h = 0; h < 128; h++) s += red[f][h];
        hout[k * NG + g0 + f] = s + b2[k];
    }
}

__global__ void final_kernel(const float* __restrict__ ho, float* __restrict__ out) {
    int g = blockIdx.x * blockDim.x + threadIdx.x;
    if (g >= NG) return;
    float o0 = ho[0 * NG + g], o1 = ho[1 * NG + g];
    float o2 = ho[2 * NG + g], o3 = ho[3 * NG + g];
    float alpha = fmaxf(softplusf(o0) + 1.f, 1.f + 1e-4f);
    float beta  = softplusf(o1);
    float nu    = softplusf(o2);
    float am1   = alpha - 1.f;
    out[0 * NG + g] = o3;
    out[1 * NG + g] = beta / am1;
    out[2 * NG + g] = beta / (am1 * nu);
    out[3 * NG + g] = nu;
    out[4 * NG + g] = alpha;
    out[5 * NG + g] = beta;
}

// ---------------- launch ----------------
extern "C" void kernel_launch(void* const* d_in, const int* in_sizes, int n_in,
                              void* d_out, int out_size) {
    const int*   z      = (const int*)  d_in[0];
    const float* pos    = (const float*)d_in[1];
    const int*   batch  = (const int*)  d_in[2];
    const int*   eidx   = (const int*)  d_in[3];
    const float* tab    = (const float*)d_in[4];
    const float* Wp     = (const float*)d_in[5];
    const float* bp     = (const float*)d_in[6];
    const float* Wcomb  = (const float*)d_in[7];
    const float* bcomb  = (const float*)d_in[8];
    const float* gW1    = (const float*)d_in[9];
    const float* gb1    = (const float*)d_in[10];
    const float* gW2    = (const float*)d_in[11];
    const float* gb2    = (const float*)d_in[12];
    const float* hW1    = (const float*)d_in[13];
    const float* hb1    = (const float*)d_in[14];
    const float* hW2    = (const float*)d_in[15];
    const float* hb2    = (const float*)d_in[16];
    float* out = (float*)d_out;

    float *x, *pool, *ho, *T, *Weff, *beff;
    uint2 *aggs, *ys;
    uint4* wt;
    int *deg, *rowptr, *cursor, *col, *part;
    cudaGetSymbolAddress((void**)&x,      g_x);
    cudaGetSymbolAddress((void**)&aggs,   g_aggs);
    cudaGetSymbolAddress((void**)&ys,     g_ys);
    cudaGetSymbolAddress((void**)&pool,   g_pool);
    cudaGetSymbolAddress((void**)&ho,     g_ho);
    cudaGetSymbolAddress((void**)&T,      g_T);
    cudaGetSymbolAddress((void**)&Weff,   g_Weff);
    cudaGetSymbolAddress((void**)&beff,   g_beff);
    cudaGetSymbolAddress((void**)&wt,     g_wt);
    cudaGetSymbolAddress((void**)&deg,    g_deg);
    cudaGetSymbolAddress((void**)&rowptr, g_rowptr);
    cudaGetSymbolAddress((void**)&cursor, g_cursor);
    cudaGetSymbolAddress((void**)&col,    g_col);
    cudaGetSymbolAddress((void**)&part,   g_part);

    cudaFuncSetAttribute(gemm_tc_kernel<true,  true >, cudaFuncAttributeMaxDynamicSharedMemorySize, GEMM_SMEM);
    cudaFuncSetAttribute(gemm_tc_kernel<true,  false>, cudaFuncAttributeMaxDynamicSharedMemorySize, GEMM_SMEM);
    cudaFuncSetAttribute(gemm_tc_kernel<false, false>, cudaFuncAttributeMaxDynamicSharedMemorySize, GEMM_SMEM);

    const int gemm_grid = (NN + 127) / 128;   // 391
    const int* src = eidx;
    const int* dst = eidx + NE;
    const size_t mat_u4 = BBYTES / 16;        // uint4 stride per matrix

    // --- precompute (weights + folded init stage) ---
    prep_weights_kernel<<<(8 * 16384 + 255) / 256, 256>>>(gW1, gW2, (__nv_bfloat16*)wt);
    prep_init_kernel<<<(104 * H + 255) / 256, 256>>>(tab, Wp, bp, Wcomb, bcomb, T, Weff, beff);
    zero_int_kernel<<<(NN + 255) / 256, 256>>>(deg, NN);
    x_init_kernel<<<(NN * 32 + 255) / 256, 256>>>(z, pos, T, Weff, beff, x);

    // --- CSR build ---
    deg_kernel<<<(NE + 255) / 256, 256>>>(dst, deg);
    partial_kernel<<<SCAN_NB, SCAN_B>>>(deg, part);
    scanpart_kernel<<<1, 512>>>(part, rowptr);
    rowptr_kernel<<<SCAN_NB, SCAN_B>>>(deg, part, rowptr, cursor);
    fill_kernel<<<(NE + 255) / 256, 256>>>(src, dst, cursor, col);

    // --- GIN layers (gather emits split agg; GEMM1 emits split y; GEMM2 emits fp32 x) ---
    for (int l = 0; l < NL; l++) {
        gather_kernel<<<(NN + 7) / 8, 256>>>(x, rowptr, col, aggs);
        gemm_tc_kernel<true, true><<<gemm_grid, 256, GEMM_SMEM>>>(
            aggs, wt + (size_t)l * mat_u4, gb1 + (size_t)l * H, nullptr, ys, NN);
        if (l < NL - 1) {
            gemm_tc_kernel<true, false><<<gemm_grid, 256, GEMM_SMEM>>>(
                ys, wt + (size_t)(4 + l) * mat_u4, gb2 + (size_t)l * H, x, nullptr, NN);
        } else {
            gemm_tc_kernel<false, false><<<gemm_grid, 256, GEMM_SMEM>>>(
                ys, wt + (size_t)(4 + l) * mat_u4, gb2 + (size_t)l * H, x, nullptr, NN);
        }
    }

    // --- pooling / heads / epilogue ---
    pool_kernel<<<NG, 128>>>(x, batch, pool);
    heads_kernel<<<dim3(4, 32), 128>>>(pool, hW1, hb1, hW2, hb2, ho);
    final_kernel<<<2, 256>>>(ho, out);
}